// round 2
// baseline (speedup 1.0000x reference)
#include <cuda_runtime.h>

// COO SpMM, rows sorted:
//   out[r, :] = sum_{e: rows[e]==r} vals[e] * seq[cols[e], :]
// Inputs: seq [50000*64 f32], vals [E f32], rows [E i32], cols [E i32]
// Output: [1, 50000, 64] f32
//
// Strategy: half-warp per edge (16 lanes x float4 = 64 features), so one
// LDG.128 warp-instruction covers 2 edges. Edge metadata packed to 16B in
// shared (single LDS.128). Segmented register accumulation, atomic flush
// only on row transitions / chunk ends.

#define D_FEAT 64
#define EDGES_PER_WARP 128
#define WARPS_PER_BLOCK 8
#define EDGES_PER_BLOCK (EDGES_PER_WARP * WARPS_PER_BLOCK)  // 1024
#define BLOCK_THREADS (WARPS_PER_BLOCK * 32)                // 256

__device__ __forceinline__ void flush_row(float* __restrict__ out,
                                          int row, int fl, const float4& acc) {
    float* p = out + row * D_FEAT + fl * 4;
    atomicAdd(p + 0, acc.x);
    atomicAdd(p + 1, acc.y);
    atomicAdd(p + 2, acc.z);
    atomicAdd(p + 3, acc.w);
}

__global__ __launch_bounds__(BLOCK_THREADS)
void spmm_seg_kernel(const float* __restrict__ seq,
                     const float* __restrict__ vals,
                     const int* __restrict__ rows,
                     const int* __restrict__ cols,
                     float* __restrict__ out,
                     int n_edges) {
    // Packed per-edge metadata: {row, col, val_bits, pad} = 16 bytes.
    __shared__ int4 s_meta[EDGES_PER_BLOCK];

    const int base = blockIdx.x * EDGES_PER_BLOCK;
    const int n    = min(EDGES_PER_BLOCK, n_edges - base);
    if (n <= 0) return;

    // Coalesced staging: each thread reads 3 scalars, writes one STS.128.
    for (int i = threadIdx.x; i < n; i += BLOCK_THREADS) {
        int4 m;
        m.x = rows[base + i];
        m.y = cols[base + i];
        m.z = __float_as_int(vals[base + i]);
        m.w = 0;
        s_meta[i] = m;
    }
    __syncthreads();

    const int warp = threadIdx.x >> 5;
    const int lane = threadIdx.x & 31;
    const int half = lane >> 4;        // 0: even edges, 1: odd edges
    const int fl   = lane & 15;        // feature lane: 4 floats each

    const int wbeg = warp * EDGES_PER_WARP;
    if (wbeg >= n) return;
    const int wend  = min(wbeg + EDGES_PER_WARP, n);
    const int first = wbeg + half;
    if (first >= wend) return;

    const float4* __restrict__ seq4 = reinterpret_cast<const float4*>(seq);

    float4 acc = make_float4(0.f, 0.f, 0.f, 0.f);
    int cur_row = s_meta[first].x;

    #pragma unroll 2
    for (int i = first; i < wend; i += 2) {
        const int4 m = s_meta[i];              // LDS.128 (broadcast per half)
        if (m.x != cur_row) {                  // half-warp-uniform, rare (~4%)
            flush_row(out, cur_row, fl, acc);
            acc = make_float4(0.f, 0.f, 0.f, 0.f);
            cur_row = m.x;
        }
        const float  v = __int_as_float(m.z);
        const float4 x = seq4[m.y * (D_FEAT / 4) + fl];  // 256B per edge, coalesced
        acc.x = fmaf(v, x.x, acc.x);
        acc.y = fmaf(v, x.y, acc.y);
        acc.z = fmaf(v, x.z, acc.z);
        acc.w = fmaf(v, x.w, acc.w);
    }
    flush_row(out, cur_row, fl, acc);
}

extern "C" void kernel_launch(void* const* d_in, const int* in_sizes, int n_in,
                              void* d_out, int out_size) {
    const float* seq  = (const float*)d_in[0];
    const float* vals = (const float*)d_in[1];
    const int*   rows = (const int*)d_in[2];
    const int*   cols = (const int*)d_in[3];
    float*       out  = (float*)d_out;
    const int n_edges = in_sizes[1];

    // Zero the poisoned output (async, graph-capturable).
    cudaMemsetAsync(out, 0, (size_t)out_size * sizeof(float));

    const int n_blocks = (n_edges + EDGES_PER_BLOCK - 1) / EDGES_PER_BLOCK;
    spmm_seg_kernel<<<n_blocks, BLOCK_THREADS>>>(seq, vals, rows, cols, out, n_edges);
}

// round 3
// speedup vs baseline: 1.1744x; 1.1744x over previous
#include <cuda_runtime.h>

// COO SpMM, rows sorted:
//   out[r, :] = sum_{e: rows[e]==r} vals[e] * seq[cols[e], :]
// Half-warp per edge (16 lanes x float4). Software-pipelined batches of 4
// edges per half-warp: all 4 gathers issued back-to-back (MLP=4) before any
// row-check branch, hiding the ~250cyc L2-hit latency.

#define D_FEAT 64
#define WARPS_PER_BLOCK 8
#define BLOCK_THREADS (WARPS_PER_BLOCK * 32)      // 256
#define N_BLOCKS 1184                              // 148 SMs * 8 = whole waves
#define EDGES_PER_BLOCK 1056                       // ceil(1.25M / 1184)
#define EDGES_PER_WARP (EDGES_PER_BLOCK / WARPS_PER_BLOCK)  // 132

__device__ __forceinline__ void flush_row(float* __restrict__ out,
                                          int row, int fl, const float4& acc) {
    float* p = out + row * D_FEAT + fl * 4;
    atomicAdd(p + 0, acc.x);
    atomicAdd(p + 1, acc.y);
    atomicAdd(p + 2, acc.z);
    atomicAdd(p + 3, acc.w);
}

__global__ __launch_bounds__(BLOCK_THREADS)
void spmm_seg_kernel(const float* __restrict__ seq,
                     const float* __restrict__ vals,
                     const int* __restrict__ rows,
                     const int* __restrict__ cols,
                     float* __restrict__ out,
                     int n_edges) {
    __shared__ int4 s_meta[EDGES_PER_BLOCK];   // {row, col, val_bits, pad}

    const int base = blockIdx.x * EDGES_PER_BLOCK;
    const int n    = min(EDGES_PER_BLOCK, n_edges - base);
    if (n <= 0) return;

    for (int i = threadIdx.x; i < n; i += BLOCK_THREADS) {
        int4 m;
        m.x = rows[base + i];
        m.y = cols[base + i];
        m.z = __float_as_int(vals[base + i]);
        m.w = 0;
        s_meta[i] = m;
    }
    __syncthreads();

    const int warp = threadIdx.x >> 5;
    const int lane = threadIdx.x & 31;
    const int half = lane >> 4;       // 0: even-indexed edges, 1: odd-indexed
    const int fl   = lane & 15;       // feature lane (4 floats)

    const int wbeg = warp * EDGES_PER_WARP;
    if (wbeg >= n) return;
    const int wend = min(wbeg + EDGES_PER_WARP, n);

    const float4* __restrict__ seq4 = reinterpret_cast<const float4*>(seq);

    int i = wbeg + half;
    if (i >= wend) return;

    float4 acc = make_float4(0.f, 0.f, 0.f, 0.f);
    int cur_row = s_meta[i].x;

    // ---- pipelined main loop: 4 edges per half-warp per iteration ----
    for (; i + 6 < wend; i += 8) {
        // Phase 1: fetch all metadata + all gathers, no branches in between.
        const int4 m0 = s_meta[i];
        const int4 m1 = s_meta[i + 2];
        const int4 m2 = s_meta[i + 4];
        const int4 m3 = s_meta[i + 6];
        const float4 x0 = seq4[m0.y * (D_FEAT / 4) + fl];
        const float4 x1 = seq4[m1.y * (D_FEAT / 4) + fl];
        const float4 x2 = seq4[m2.y * (D_FEAT / 4) + fl];
        const float4 x3 = seq4[m3.y * (D_FEAT / 4) + fl];

        // Phase 2: segmented accumulation (row-uniform per half-warp).
        if (m0.x != cur_row) { flush_row(out, cur_row, fl, acc); acc = make_float4(0,0,0,0); cur_row = m0.x; }
        float v = __int_as_float(m0.z);
        acc.x = fmaf(v, x0.x, acc.x); acc.y = fmaf(v, x0.y, acc.y);
        acc.z = fmaf(v, x0.z, acc.z); acc.w = fmaf(v, x0.w, acc.w);

        if (m1.x != cur_row) { flush_row(out, cur_row, fl, acc); acc = make_float4(0,0,0,0); cur_row = m1.x; }
        v = __int_as_float(m1.z);
        acc.x = fmaf(v, x1.x, acc.x); acc.y = fmaf(v, x1.y, acc.y);
        acc.z = fmaf(v, x1.z, acc.z); acc.w = fmaf(v, x1.w, acc.w);

        if (m2.x != cur_row) { flush_row(out, cur_row, fl, acc); acc = make_float4(0,0,0,0); cur_row = m2.x; }
        v = __int_as_float(m2.z);
        acc.x = fmaf(v, x2.x, acc.x); acc.y = fmaf(v, x2.y, acc.y);
        acc.z = fmaf(v, x2.z, acc.z); acc.w = fmaf(v, x2.w, acc.w);

        if (m3.x != cur_row) { flush_row(out, cur_row, fl, acc); acc = make_float4(0,0,0,0); cur_row = m3.x; }
        v = __int_as_float(m3.z);
        acc.x = fmaf(v, x3.x, acc.x); acc.y = fmaf(v, x3.y, acc.y);
        acc.z = fmaf(v, x3.z, acc.z); acc.w = fmaf(v, x3.w, acc.w);
    }

    // ---- remainder ----
    for (; i < wend; i += 2) {
        const int4 m = s_meta[i];
        const float4 x = seq4[m.y * (D_FEAT / 4) + fl];
        if (m.x != cur_row) { flush_row(out, cur_row, fl, acc); acc = make_float4(0,0,0,0); cur_row = m.x; }
        const float v = __int_as_float(m.z);
        acc.x = fmaf(v, x.x, acc.x); acc.y = fmaf(v, x.y, acc.y);
        acc.z = fmaf(v, x.z, acc.z); acc.w = fmaf(v, x.w, acc.w);
    }

    flush_row(out, cur_row, fl, acc);
}

extern "C" void kernel_launch(void* const* d_in, const int* in_sizes, int n_in,
                              void* d_out, int out_size) {
    const float* seq  = (const float*)d_in[0];
    const float* vals = (const float*)d_in[1];
    const int*   rows = (const int*)d_in[2];
    const int*   cols = (const int*)d_in[3];
    float*       out  = (float*)d_out;
    const int n_edges = in_sizes[1];

    cudaMemsetAsync(out, 0, (size_t)out_size * sizeof(float));

    // Fixed grid sized for whole waves; covers up to N_BLOCKS*EDGES_PER_BLOCK
    // = 1,250,304 edges >= 1,250,000.
    spmm_seg_kernel<<<N_BLOCKS, BLOCK_THREADS>>>(seq, vals, rows, cols, out, n_edges);
}

// round 4
// speedup vs baseline: 1.2230x; 1.0414x over previous
#include <cuda_runtime.h>

// COO SpMM with sorted rows -> CSR two-phase, no atomics / no smem / no memset.
//   Phase A: row_ptr[r] = lower_bound(rows, r)   (binary search per row)
//   Phase B: warp per row; lane owns 2 features (float2); register accumulate;
//            one coalesced non-atomic store per row (covers empty rows = 0).
// Inputs: seq [50000*64 f32], vals [E f32], rows [E i32], cols [E i32]
// Output: [1, 50000, 64] f32

#define D_FEAT 64
#define MAX_NODES 50001

__device__ int g_row_ptr[MAX_NODES + 1];

__global__ void build_row_ptr_kernel(const int* __restrict__ rows,
                                     int n_edges, int n_nodes) {
    int r = blockIdx.x * blockDim.x + threadIdx.x;
    if (r > n_nodes) return;
    // lower_bound of r in sorted rows[]
    int lo = 0, hi = n_edges;
    while (lo < hi) {
        int mid = (lo + hi) >> 1;
        if (rows[mid] < r) lo = mid + 1; else hi = mid;
    }
    g_row_ptr[r] = lo;
}

__global__ __launch_bounds__(256)
void spmm_csr_kernel(const float* __restrict__ seq,
                     const float* __restrict__ vals,
                     const int* __restrict__ cols,
                     float* __restrict__ out,
                     int n_nodes) {
    const int warp = (blockIdx.x * blockDim.x + threadIdx.x) >> 5;
    const int lane = threadIdx.x & 31;
    if (warp >= n_nodes) return;

    const int beg = g_row_ptr[warp];
    const int end = g_row_ptr[warp + 1];

    const float2* __restrict__ seq2 = reinterpret_cast<const float2*>(seq);

    float2 acc = make_float2(0.f, 0.f);

    for (int j = beg; j < end; j += 32) {
        // Coalesced tile load of edge metadata (one LDG.32 each per lane).
        const int idx = j + lane;
        int   c = 0;
        float v = 0.f;
        if (idx < end) { c = cols[idx]; v = vals[idx]; }
        const int cnt = min(32, end - j);

        int jj = 0;
        // 4 edges per step: 8 shfl broadcasts, then 4 back-to-back LDG.64
        // gathers (MLP=4), then FMAs. No branches between the loads.
        for (; jj + 4 <= cnt; jj += 4) {
            const int   c0 = __shfl_sync(0xffffffffu, c, jj);
            const int   c1 = __shfl_sync(0xffffffffu, c, jj + 1);
            const int   c2 = __shfl_sync(0xffffffffu, c, jj + 2);
            const int   c3 = __shfl_sync(0xffffffffu, c, jj + 3);
            const float v0 = __shfl_sync(0xffffffffu, v, jj);
            const float v1 = __shfl_sync(0xffffffffu, v, jj + 1);
            const float v2 = __shfl_sync(0xffffffffu, v, jj + 2);
            const float v3 = __shfl_sync(0xffffffffu, v, jj + 3);

            const float2 x0 = seq2[c0 * (D_FEAT / 2) + lane];
            const float2 x1 = seq2[c1 * (D_FEAT / 2) + lane];
            const float2 x2 = seq2[c2 * (D_FEAT / 2) + lane];
            const float2 x3 = seq2[c3 * (D_FEAT / 2) + lane];

            acc.x = fmaf(v0, x0.x, acc.x); acc.y = fmaf(v0, x0.y, acc.y);
            acc.x = fmaf(v1, x1.x, acc.x); acc.y = fmaf(v1, x1.y, acc.y);
            acc.x = fmaf(v2, x2.x, acc.x); acc.y = fmaf(v2, x2.y, acc.y);
            acc.x = fmaf(v3, x3.x, acc.x); acc.y = fmaf(v3, x3.y, acc.y);
        }
        for (; jj < cnt; ++jj) {
            const int   cj = __shfl_sync(0xffffffffu, c, jj);
            const float vj = __shfl_sync(0xffffffffu, v, jj);
            const float2 x = seq2[cj * (D_FEAT / 2) + lane];
            acc.x = fmaf(vj, x.x, acc.x);
            acc.y = fmaf(vj, x.y, acc.y);
        }
    }

    // Single coalesced store per row; empty rows write zeros (no memset pass).
    reinterpret_cast<float2*>(out)[warp * (D_FEAT / 2) + lane] = acc;
}

extern "C" void kernel_launch(void* const* d_in, const int* in_sizes, int n_in,
                              void* d_out, int out_size) {
    const float* seq  = (const float*)d_in[0];
    const float* vals = (const float*)d_in[1];
    const int*   rows = (const int*)d_in[2];
    const int*   cols = (const int*)d_in[3];
    float*       out  = (float*)d_out;
    const int n_edges = in_sizes[1];
    const int n_nodes = out_size / D_FEAT;   // 50000

    // Phase A: row_ptr via binary search (n_nodes+1 entries).
    const int tA = 256;
    build_row_ptr_kernel<<<(n_nodes + 1 + tA) / tA, tA>>>(rows, n_edges, n_nodes);

    // Phase B: one warp per row, 8 rows per 256-thread block.
    const int rows_per_block = 256 / 32;
    spmm_csr_kernel<<<(n_nodes + rows_per_block - 1) / rows_per_block, 256>>>(
        seq, vals, cols, out, n_nodes);
}